// round 2
// baseline (speedup 1.0000x reference)
#include <cuda_runtime.h>
#include <math.h>

#define B_   64
#define L_   32
#define D_   1024
#define DFF  2048
#define K_   128
#define N_   256

// ---------------- scratch (no allocations allowed) ----------------
__device__ float g_A[N_ * N_];              // normalized A  [i][j]
__device__ float g_W[N_ * K_ * K_];         // normalized W  [t][i][o]
__device__ float g_xr[B_ * N_ * K_];        // LN'd kronecker input
__device__ float g_xloc[B_ * N_ * K_];      // x_local [b][n][o]
__device__ float g_xln[B_ * K_ * N_];       // transposed+LN [b][k][n]
__device__ float g_xglob[B_ * K_ * N_];     // x_global [b][k][n]
__device__ float g_mixed[B_ * L_ * D_];
__device__ float g_G[B_ * L_ * DFF];        // gate raw
__device__ float g_U[B_ * L_ * DFF];        // up raw
__device__ float g_H[B_ * L_ * DFF];        // silu(gate)*up
__device__ float g_ffn[B_ * L_ * D_];

// ---------------- packed f32x2 helpers (FFMA2 path) ----------------
__device__ __forceinline__ unsigned long long dup2(float v) {
    unsigned long long r;
    asm("mov.b64 %0, {%1, %1};" : "=l"(r) : "f"(v));
    return r;
}
__device__ __forceinline__ void fma2(unsigned long long& d, unsigned long long a,
                                     unsigned long long b) {
    asm("fma.rn.f32x2 %0, %1, %2, %0;" : "+l"(d) : "l"(a), "l"(b));
}
__device__ __forceinline__ void unpack2(unsigned long long v, float& x, float& y) {
    asm("mov.b64 {%0, %1}, %2;" : "=f"(x), "=f"(y) : "l"(v));
}

// ---------------- helpers ----------------
__device__ __forceinline__ void blockReduce2_256(float& s1, float& s2) {
    __shared__ float sh1[8], sh2[8];
    int t = threadIdx.x;
    #pragma unroll
    for (int o = 16; o > 0; o >>= 1) {
        s1 += __shfl_xor_sync(0xffffffffu, s1, o);
        s2 += __shfl_xor_sync(0xffffffffu, s2, o);
    }
    if ((t & 31) == 0) { sh1[t >> 5] = s1; sh2[t >> 5] = s2; }
    __syncthreads();
    float a = 0.f, b = 0.f;
    #pragma unroll
    for (int w = 0; w < 8; w++) { a += sh1[w]; b += sh2[w]; }
    s1 = a; s2 = b;
    __syncthreads();
}

// ---------------- K0: A = A_logits / max(||col||, eps) ----------------
__global__ void k_prepA(const float* __restrict__ Al) {
    int j = blockIdx.x;
    int i = threadIdx.x;
    float v = Al[i * N_ + j];
    float s1 = v * v, s2 = 0.f;
    blockReduce2_256(s1, s2);
    float inv = 1.f / fmaxf(sqrtf(s1), 1e-12f);
    g_A[i * N_ + j] = v * inv;
}

// ---------------- K1: W[t] = norm_cols( sum_k W1[t,k] * WV[k] ) ----------------
__global__ void k_prepW(const float* __restrict__ W1, const float* __restrict__ WV) {
    int t = blockIdx.x;
    int o = threadIdx.x;
    float w1[8];
    #pragma unroll
    for (int k = 0; k < 8; k++) w1[k] = W1[t * 8 + k];
    float ss = 0.f;
    for (int i = 0; i < K_; i++) {
        float wl = 0.f;
        #pragma unroll
        for (int k = 0; k < 8; k++) wl += w1[k] * WV[(k * K_ + i) * K_ + o];
        ss += wl * wl;
    }
    float inv = 1.f / fmaxf(sqrtf(ss), 1e-12f);
    for (int i = 0; i < K_; i++) {
        float wl = 0.f;
        #pragma unroll
        for (int k = 0; k < 8; k++) wl += w1[k] * WV[(k * K_ + i) * K_ + o];
        g_W[(t * K_ + i) * K_ + o] = wl * inv;
    }
}

// ---------------- K2: xr = LN128( x + LN_D(y) ) ----------------
__global__ void k_xr(const float* __restrict__ x, const float* __restrict__ y,
                     const float* __restrict__ nyg, const float* __restrict__ nyb,
                     const float* __restrict__ kn1g, const float* __restrict__ kn1b) {
    int row = blockIdx.x;
    int t = threadIdx.x;
    const float* yr = y + (size_t)row * D_;
    const float* xp = x + (size_t)row * D_;
    float yv[4];
    float s1 = 0.f, s2 = 0.f;
    #pragma unroll
    for (int e = 0; e < 4; e++) {
        float v = yr[t * 4 + e];
        yv[e] = v; s1 += v; s2 += v * v;
    }
    blockReduce2_256(s1, s2);
    float m = s1 * (1.f / D_);
    float var = s2 * (1.f / D_) - m * m;
    float rs = rsqrtf(var + 1e-5f);
    float kin[4];
    float ls1 = 0.f, ls2 = 0.f;
    #pragma unroll
    for (int e = 0; e < 4; e++) {
        int d = t * 4 + e;
        float ny = (yv[e] - m) * rs * nyg[d] + nyb[d];
        float kv = xp[d] + ny;
        kin[e] = kv; ls1 += kv; ls2 += kv * kv;
    }
    #pragma unroll
    for (int o = 16; o > 0; o >>= 1) {
        ls1 += __shfl_xor_sync(0xffffffffu, ls1, o);
        ls2 += __shfl_xor_sync(0xffffffffu, ls2, o);
    }
    float lm = ls1 * (1.f / 128.f);
    float lv = ls2 * (1.f / 128.f) - lm * lm;
    float lrs = rsqrtf(lv + 1e-5f);
    #pragma unroll
    for (int e = 0; e < 4; e++) {
        int d = t * 4 + e;
        int i = d & 127;
        g_xr[(size_t)row * D_ + d] = (kin[e] - lm) * lrs * kn1g[i] + kn1b[i];
    }
}

// ---------------- K3: x_local[b,n,o] = sum_i xr[b,n,i] * W[n,i,o] ----------------
#define BG 16
__global__ void k_xlocal() {
    int n  = blockIdx.x;
    int b0 = blockIdx.y * BG;
    int o  = threadIdx.x;
    __shared__ float xs[BG][K_];
    #pragma unroll
    for (int bb = 0; bb < BG; bb++)
        xs[bb][o] = g_xr[((size_t)(b0 + bb) * N_ + n) * K_ + o];
    __syncthreads();
    float acc[BG];
    #pragma unroll
    for (int bb = 0; bb < BG; bb++) acc[bb] = 0.f;
    const float* Wn = g_W + (size_t)n * K_ * K_;
    for (int i = 0; i < K_; i++) {
        float w = Wn[i * K_ + o];
        #pragma unroll
        for (int bb = 0; bb < BG; bb++) acc[bb] += xs[bb][i] * w;
    }
    #pragma unroll
    for (int bb = 0; bb < BG; bb++)
        g_xloc[((size_t)(b0 + bb) * N_ + n) * K_ + o] = acc[bb];
}

// ---------------- K4a: transpose + LN over N (kn2) ----------------
__global__ void k_trln(const float* __restrict__ kn2g, const float* __restrict__ kn2b) {
    int k = blockIdx.x;
    int b = blockIdx.y;
    int n = threadIdx.x;
    float v = g_xloc[((size_t)b * N_ + n) * K_ + k];
    float s1 = v, s2 = v * v;
    blockReduce2_256(s1, s2);
    float m = s1 * (1.f / N_);
    float var = s2 * (1.f / N_) - m * m;
    float rs = rsqrtf(var + 1e-5f);
    g_xln[((size_t)b * K_ + k) * N_ + n] = (v - m) * rs * kn2g[n] + kn2b[n];
}

// ---------------- K4b: x_global = x_ln @ A ----------------
__global__ void k_xglob() {
    int b  = blockIdx.x;
    int kg = blockIdx.y;
    int m  = threadIdx.x;
    __shared__ float rows[16][N_];
    #pragma unroll
    for (int kk = 0; kk < 16; kk++)
        rows[kk][m] = g_xln[((size_t)b * K_ + kg * 16 + kk) * N_ + m];
    __syncthreads();
    float acc[16];
    #pragma unroll
    for (int kk = 0; kk < 16; kk++) acc[kk] = 0.f;
    for (int nn = 0; nn < N_; nn++) {
        float a = g_A[nn * N_ + m];
        #pragma unroll
        for (int kk = 0; kk < 16; kk++) acc[kk] += rows[kk][nn] * a;
    }
    #pragma unroll
    for (int kk = 0; kk < 16; kk++)
        g_xglob[((size_t)b * K_ + kg * 16 + kk) * N_ + m] = acc[kk];
}

// ---------------- K5: mixed = LN( x + 0.5*rule + 0.5*kron , n1) ----------------
__global__ void k_mixed(const float* __restrict__ x,
                        const float* __restrict__ n1g, const float* __restrict__ n1b) {
    int row = blockIdx.x;
    int b = row >> 5, l = row & 31;
    int t = threadIdx.x;
    float v[4];
    float s1 = 0.f, s2 = 0.f;
    #pragma unroll
    for (int e = 0; e < 4; e++) {
        int d = t * 4 + e;
        float rule = x[((size_t)b * L_ + (d >> 5)) * D_ + l * 32 + (d & 31)];
        float kron = g_xglob[(size_t)row * D_ + d];
        float xv   = x[(size_t)row * D_ + d];
        float val = xv + 0.5f * rule + 0.5f * kron;
        v[e] = val; s1 += val; s2 += val * val;
    }
    blockReduce2_256(s1, s2);
    float m = s1 * (1.f / D_);
    float var = s2 * (1.f / D_) - m * m;
    float rs = rsqrtf(var + 1e-5f);
    #pragma unroll
    for (int e = 0; e < 4; e++) {
        int d = t * 4 + e;
        g_mixed[(size_t)row * D_ + d] = (v[e] - m) * rs * n1g[d] + n1b[d];
    }
}

// ---------------- K6: gate / up GEMM with packed f32x2 FMA ----------------
// Per (l, nt, z): C[64 x 256] = mixed_l[64 x 1024] @ W_z[l][1024 x (256 slice)]
// 256 threads, thread tile 8 rows x 8 cols as 32 f32x2 accumulators.
__global__ __launch_bounds__(256, 2) void k_gu(const float* __restrict__ Wg,
                                               const float* __restrict__ Wu) {
    int l  = blockIdx.x;
    int nt = blockIdx.y;
    const float* Bsrc = blockIdx.z ? Wu : Wg;
    float* Out        = blockIdx.z ? g_U : g_G;
    int t  = threadIdx.x;
    int tx = t & 31, ty = t >> 5;      // 32 x 8
    __shared__ float As[32][68];       // [k][m] transposed
    __shared__ float Bs[32][256];      // [k][n]
    unsigned long long acc[8][4];
    #pragma unroll
    for (int i = 0; i < 8; i++)
        #pragma unroll
        for (int j = 0; j < 4; j++) acc[i][j] = 0ull;

    const float* Ap = g_mixed + (size_t)l * D_;                 // row stride L_*D_
    const float* Bp = Bsrc + (size_t)l * D_ * DFF + nt * 256;   // row stride DFF

    for (int k0 = 0; k0 < D_; k0 += 32) {
        // As: 64 rows x 32 k = 512 float4
        #pragma unroll
        for (int q = t; q < 512; q += 256) {
            int rb = q >> 3, c4 = (q & 7) * 4;
            float4 v = *(const float4*)(Ap + (size_t)rb * (L_ * D_) + k0 + c4);
            As[c4 + 0][rb] = v.x; As[c4 + 1][rb] = v.y;
            As[c4 + 2][rb] = v.z; As[c4 + 3][rb] = v.w;
        }
        // Bs: 32 k x 256 n = 2048 float4
        #pragma unroll
        for (int q = t; q < 2048; q += 256) {
            int rk = q >> 6, c4 = (q & 63) * 4;
            *(float4*)&Bs[rk][c4] = *(const float4*)(Bp + (size_t)(k0 + rk) * DFF + c4);
        }
        __syncthreads();
        #pragma unroll 4
        for (int kk = 0; kk < 32; kk++) {
            float4 a0 = *(const float4*)&As[kk][ty * 8];
            float4 a1 = *(const float4*)&As[kk][ty * 8 + 4];
            unsigned long long ad[8];
            ad[0] = dup2(a0.x); ad[1] = dup2(a0.y); ad[2] = dup2(a0.z); ad[3] = dup2(a0.w);
            ad[4] = dup2(a1.x); ad[5] = dup2(a1.y); ad[6] = dup2(a1.z); ad[7] = dup2(a1.w);
            const ulonglong2* bp2 = (const ulonglong2*)&Bs[kk][tx * 8];
            ulonglong2 b01 = bp2[0], b23 = bp2[1];
            unsigned long long bv0 = b01.x, bv1 = b01.y, bv2 = b23.x, bv3 = b23.y;
            #pragma unroll
            for (int i = 0; i < 8; i++) {
                fma2(acc[i][0], ad[i], bv0);
                fma2(acc[i][1], ad[i], bv1);
                fma2(acc[i][2], ad[i], bv2);
                fma2(acc[i][3], ad[i], bv3);
            }
        }
        __syncthreads();
    }
    #pragma unroll
    for (int i = 0; i < 8; i++) {
        int b = ty * 8 + i;
        float* op = Out + ((size_t)b * L_ + l) * DFF + nt * 256 + tx * 8;
        #pragma unroll
        for (int j = 0; j < 4; j++) {
            float x0, x1;
            unpack2(acc[i][j], x0, x1);
            op[2 * j] = x0; op[2 * j + 1] = x1;
        }
    }
}

// ---------------- K6b: H = silu(G) * U ----------------
__global__ void k_act() {
    int idx = blockIdx.x * 256 + threadIdx.x;   // one float4 each
    float4 g = ((const float4*)g_G)[idx];
    float4 u = ((const float4*)g_U)[idx];
    float4 h;
    h.x = g.x / (1.f + expf(-g.x)) * u.x;
    h.y = g.y / (1.f + expf(-g.y)) * u.y;
    h.z = g.z / (1.f + expf(-g.z)) * u.z;
    h.w = g.w / (1.f + expf(-g.w)) * u.w;
    ((float4*)g_H)[idx] = h;
}

// ---------------- K7: down GEMM with packed f32x2 FMA ----------------
__global__ __launch_bounds__(256, 2) void k_dn(const float* __restrict__ Wd) {
    int l  = blockIdx.x;
    int nt = blockIdx.y;
    int t  = threadIdx.x;
    int tx = t & 31, ty = t >> 5;
    __shared__ float As[32][68];
    __shared__ float Bs[32][256];
    unsigned long long acc[8][4];
    #pragma unroll
    for (int i = 0; i < 8; i++)
        #pragma unroll
        for (int j = 0; j < 4; j++) acc[i][j] = 0ull;

    const float* Ap = g_H + (size_t)l * DFF;                    // row stride L_*DFF
    const float* Bp = Wd + (size_t)l * DFF * D_ + nt * 256;     // row stride D_

    for (int k0 = 0; k0 < DFF; k0 += 32) {
        #pragma unroll
        for (int q = t; q < 512; q += 256) {
            int rb = q >> 3, c4 = (q & 7) * 4;
            float4 v = *(const float4*)(Ap + (size_t)rb * (L_ * DFF) + k0 + c4);
            As[c4 + 0][rb] = v.x; As[c4 + 1][rb] = v.y;
            As[c4 + 2][rb] = v.z; As[c4 + 3][rb] = v.w;
        }
        #pragma unroll
        for (int q = t; q < 2048; q += 256) {
            int rk = q >> 6, c4 = (q & 63) * 4;
            *(float4*)&Bs[rk][c4] = *(const float4*)(Bp + (size_t)(k0 + rk) * D_ + c4);
        }
        __syncthreads();
        #pragma unroll 4
        for (int kk = 0; kk < 32; kk++) {
            float4 a0 = *(const float4*)&As[kk][ty * 8];
            float4 a1 = *(const float4*)&As[kk][ty * 8 + 4];
            unsigned long long ad[8];
            ad[0] = dup2(a0.x); ad[1] = dup2(a0.y); ad[2] = dup2(a0.z); ad[3] = dup2(a0.w);
            ad[4] = dup2(a1.x); ad[5] = dup2(a1.y); ad[6] = dup2(a1.z); ad[7] = dup2(a1.w);
            const ulonglong2* bp2 = (const ulonglong2*)&Bs[kk][tx * 8];
            ulonglong2 b01 = bp2[0], b23 = bp2[1];
            unsigned long long bv0 = b01.x, bv1 = b01.y, bv2 = b23.x, bv3 = b23.y;
            #pragma unroll
            for (int i = 0; i < 8; i++) {
                fma2(acc[i][0], ad[i], bv0);
                fma2(acc[i][1], ad[i], bv1);
                fma2(acc[i][2], ad[i], bv2);
                fma2(acc[i][3], ad[i], bv3);
            }
        }
        __syncthreads();
    }
    #pragma unroll
    for (int i = 0; i < 8; i++) {
        int b = ty * 8 + i;
        float* op = g_ffn + ((size_t)b * L_ + l) * D_ + nt * 256 + tx * 8;
        #pragma unroll
        for (int j = 0; j < 4; j++) {
            float x0, x1;
            unpack2(acc[i][j], x0, x1);
            op[2 * j] = x0; op[2 * j + 1] = x1;
        }
    }
}

// ---------------- K8: out = LN(mixed+ffn, n2); y_out = y + ffn ----------------
__global__ void k_final(const float* __restrict__ y,
                        const float* __restrict__ n2g, const float* __restrict__ n2b,
                        float* __restrict__ out) {
    int row = blockIdx.x;
    int t = threadIdx.x;
    float v[4], fv[4];
    float s1 = 0.f, s2 = 0.f;
    #pragma unroll
    for (int e = 0; e < 4; e++) {
        int d = t * 4 + e;
        size_t idx = (size_t)row * D_ + d;
        float f = g_ffn[idx];
        float val = g_mixed[idx] + f;
        v[e] = val; fv[e] = f; s1 += val; s2 += val * val;
    }
    blockReduce2_256(s1, s2);
    float m = s1 * (1.f / D_);
    float var = s2 * (1.f / D_) - m * m;
    float rs = rsqrtf(var + 1e-5f);
    #pragma unroll
    for (int e = 0; e < 4; e++) {
        int d = t * 4 + e;
        size_t idx = (size_t)row * D_ + d;
        out[idx] = (v[e] - m) * rs * n2g[d] + n2b[d];
        out[(size_t)B_ * L_ * D_ + idx] = y[idx] + fv[e];
    }
}

// ---------------- launch ----------------
extern "C" void kernel_launch(void* const* d_in, const int* in_sizes, int n_in,
                              void* d_out, int out_size) {
    const float* x       = (const float*)d_in[0];
    const float* y       = (const float*)d_in[1];
    const float* A_log   = (const float*)d_in[2];
    const float* W_1     = (const float*)d_in[3];
    const float* W_V     = (const float*)d_in[4];
    const float* kn1_g   = (const float*)d_in[5];
    const float* kn1_b   = (const float*)d_in[6];
    const float* kn2_g   = (const float*)d_in[7];
    const float* kn2_b   = (const float*)d_in[8];
    const float* W_gate  = (const float*)d_in[9];
    const float* W_up    = (const float*)d_in[10];
    const float* W_down  = (const float*)d_in[11];
    const float* ny_g    = (const float*)d_in[12];
    const float* ny_b    = (const float*)d_in[13];
    const float* n1_g    = (const float*)d_in[14];
    const float* n1_b    = (const float*)d_in[15];
    const float* n2_g    = (const float*)d_in[16];
    const float* n2_b    = (const float*)d_in[17];
    float* out = (float*)d_out;

    k_prepA<<<N_, 256>>>(A_log);
    k_prepW<<<N_, 128>>>(W_1, W_V);
    k_xr<<<B_ * L_, 256>>>(x, y, ny_g, ny_b, kn1_g, kn1_b);
    k_xlocal<<<dim3(N_, B_ / BG), 128>>>();
    k_trln<<<dim3(K_, B_), 256>>>(kn2_g, kn2_b);
    k_xglob<<<dim3(B_, 8), 256>>>();
    k_mixed<<<B_ * L_, 256>>>(x, n1_g, n1_b);
    k_gu<<<dim3(L_, DFF / 256, 2), 256>>>(W_gate, W_up);
    k_act<<<(B_ * L_ * DFF) / (256 * 4), 256>>>();
    k_dn<<<dim3(L_, D_ / 256), 256>>>(W_down);
    k_final<<<B_ * L_, 256>>>(y, n2_g, n2_b, out);
}

// round 3
// speedup vs baseline: 1.5906x; 1.5906x over previous
#include <cuda_runtime.h>
#include <math.h>

#define B_   64
#define L_   32
#define D_   1024
#define DFF  2048
#define K_   128
#define N_   256

// ---------------- scratch (no allocations allowed) ----------------
__device__ float g_A[N_ * N_];
__device__ float g_W[N_ * K_ * K_];
__device__ float g_xr[B_ * N_ * K_];
__device__ float g_xloc[B_ * N_ * K_];
__device__ float g_xln[B_ * K_ * N_];
__device__ float g_xglob[B_ * K_ * N_];
__device__ float g_mixed[B_ * L_ * D_];
__device__ float g_G[B_ * L_ * DFF];
__device__ float g_U[B_ * L_ * DFF];
__device__ float g_H[B_ * L_ * DFF];
__device__ float g_ffn[B_ * L_ * D_];

// ---------------- helpers ----------------
__device__ __forceinline__ void blockReduce2_256(float& s1, float& s2) {
    __shared__ float sh1[8], sh2[8];
    int t = threadIdx.x;
    #pragma unroll
    for (int o = 16; o > 0; o >>= 1) {
        s1 += __shfl_xor_sync(0xffffffffu, s1, o);
        s2 += __shfl_xor_sync(0xffffffffu, s2, o);
    }
    if ((t & 31) == 0) { sh1[t >> 5] = s1; sh2[t >> 5] = s2; }
    __syncthreads();
    float a = 0.f, b = 0.f;
    #pragma unroll
    for (int w = 0; w < 8; w++) { a += sh1[w]; b += sh2[w]; }
    s1 = a; s2 = b;
    __syncthreads();
}

// split fp32 -> (bf16 hi, bf16 lo) packed pairs; x0 -> low half, x1 -> high half
__device__ __forceinline__ void cvt_split(float x0, float x1, unsigned& hi, unsigned& lo) {
    unsigned h;
    asm("cvt.rn.bf16x2.f32 %0, %1, %2;" : "=r"(h) : "f"(x1), "f"(x0));
    float h0 = __uint_as_float(h << 16);
    float h1 = __uint_as_float(h & 0xffff0000u);
    float l0 = x0 - h0;
    float l1 = x1 - h1;
    unsigned l;
    asm("cvt.rn.bf16x2.f32 %0, %1, %2;" : "=r"(l) : "f"(l1), "f"(l0));
    hi = h; lo = l;
}

__device__ __forceinline__ void mma16816(float* c, const unsigned* a, unsigned b0, unsigned b1) {
    asm volatile(
        "mma.sync.aligned.m16n8k16.row.col.f32.bf16.bf16.f32 "
        "{%0,%1,%2,%3}, {%4,%5,%6,%7}, {%8,%9}, {%0,%1,%2,%3};"
        : "+f"(c[0]), "+f"(c[1]), "+f"(c[2]), "+f"(c[3])
        : "r"(a[0]), "r"(a[1]), "r"(a[2]), "r"(a[3]), "r"(b0), "r"(b1));
}

// ---------------- K0: A = A_logits / max(||col||, eps) ----------------
__global__ void k_prepA(const float* __restrict__ Al) {
    int j = blockIdx.x;
    int i = threadIdx.x;
    float v = Al[i * N_ + j];
    float s1 = v * v, s2 = 0.f;
    blockReduce2_256(s1, s2);
    float inv = 1.f / fmaxf(sqrtf(s1), 1e-12f);
    g_A[i * N_ + j] = v * inv;
}

// ---------------- K1: W[t] = norm_cols( sum_k W1[t,k] * WV[k] ) ----------------
__global__ void k_prepW(const float* __restrict__ W1, const float* __restrict__ WV) {
    int t = blockIdx.x;
    int o = threadIdx.x;
    float w1[8];
    #pragma unroll
    for (int k = 0; k < 8; k++) w1[k] = W1[t * 8 + k];
    float ss = 0.f;
    for (int i = 0; i < K_; i++) {
        float wl = 0.f;
        #pragma unroll
        for (int k = 0; k < 8; k++) wl += w1[k] * WV[(k * K_ + i) * K_ + o];
        ss += wl * wl;
    }
    float inv = 1.f / fmaxf(sqrtf(ss), 1e-12f);
    for (int i = 0; i < K_; i++) {
        float wl = 0.f;
        #pragma unroll
        for (int k = 0; k < 8; k++) wl += w1[k] * WV[(k * K_ + i) * K_ + o];
        g_W[(t * K_ + i) * K_ + o] = wl * inv;
    }
}

// ---------------- K2: xr = LN128( x + LN_D(y) ) ----------------
__global__ void k_xr(const float* __restrict__ x, const float* __restrict__ y,
                     const float* __restrict__ nyg, const float* __restrict__ nyb,
                     const float* __restrict__ kn1g, const float* __restrict__ kn1b) {
    int row = blockIdx.x;
    int t = threadIdx.x;
    const float* yr = y + (size_t)row * D_;
    const float* xp = x + (size_t)row * D_;
    float yv[4];
    float s1 = 0.f, s2 = 0.f;
    #pragma unroll
    for (int e = 0; e < 4; e++) {
        float v = yr[t * 4 + e];
        yv[e] = v; s1 += v; s2 += v * v;
    }
    blockReduce2_256(s1, s2);
    float m = s1 * (1.f / D_);
    float var = s2 * (1.f / D_) - m * m;
    float rs = rsqrtf(var + 1e-5f);
    float kin[4];
    float ls1 = 0.f, ls2 = 0.f;
    #pragma unroll
    for (int e = 0; e < 4; e++) {
        int d = t * 4 + e;
        float ny = (yv[e] - m) * rs * nyg[d] + nyb[d];
        float kv = xp[d] + ny;
        kin[e] = kv; ls1 += kv; ls2 += kv * kv;
    }
    #pragma unroll
    for (int o = 16; o > 0; o >>= 1) {
        ls1 += __shfl_xor_sync(0xffffffffu, ls1, o);
        ls2 += __shfl_xor_sync(0xffffffffu, ls2, o);
    }
    float lm = ls1 * (1.f / 128.f);
    float lv = ls2 * (1.f / 128.f) - lm * lm;
    float lrs = rsqrtf(lv + 1e-5f);
    #pragma unroll
    for (int e = 0; e < 4; e++) {
        int d = t * 4 + e;
        int i = d & 127;
        g_xr[(size_t)row * D_ + d] = (kin[e] - lm) * lrs * kn1g[i] + kn1b[i];
    }
}

// ---------------- K3: x_local[b,n,o] = sum_i xr[b,n,i] * W[n,i,o] ----------------
#define BG 16
__global__ void k_xlocal() {
    int n  = blockIdx.x;
    int b0 = blockIdx.y * BG;
    int o  = threadIdx.x;
    __shared__ float xs[BG][K_];
    #pragma unroll
    for (int bb = 0; bb < BG; bb++)
        xs[bb][o] = g_xr[((size_t)(b0 + bb) * N_ + n) * K_ + o];
    __syncthreads();
    float acc[BG];
    #pragma unroll
    for (int bb = 0; bb < BG; bb++) acc[bb] = 0.f;
    const float* Wn = g_W + (size_t)n * K_ * K_;
    for (int i = 0; i < K_; i++) {
        float w = Wn[i * K_ + o];
        #pragma unroll
        for (int bb = 0; bb < BG; bb++) acc[bb] += xs[bb][i] * w;
    }
    #pragma unroll
    for (int bb = 0; bb < BG; bb++)
        g_xloc[((size_t)(b0 + bb) * N_ + n) * K_ + o] = acc[bb];
}

// ---------------- K4a: transpose + LN over N (kn2) ----------------
__global__ void k_trln(const float* __restrict__ kn2g, const float* __restrict__ kn2b) {
    int k = blockIdx.x;
    int b = blockIdx.y;
    int n = threadIdx.x;
    float v = g_xloc[((size_t)b * N_ + n) * K_ + k];
    float s1 = v, s2 = v * v;
    blockReduce2_256(s1, s2);
    float m = s1 * (1.f / N_);
    float var = s2 * (1.f / N_) - m * m;
    float rs = rsqrtf(var + 1e-5f);
    g_xln[((size_t)b * K_ + k) * N_ + n] = (v - m) * rs * kn2g[n] + kn2b[n];
}

// ---------------- K4b: x_global = x_ln @ A ----------------
__global__ void k_xglob() {
    int b  = blockIdx.x;
    int kg = blockIdx.y;
    int m  = threadIdx.x;
    __shared__ float rows[16][N_];
    #pragma unroll
    for (int kk = 0; kk < 16; kk++)
        rows[kk][m] = g_xln[((size_t)b * K_ + kg * 16 + kk) * N_ + m];
    __syncthreads();
    float acc[16];
    #pragma unroll
    for (int kk = 0; kk < 16; kk++) acc[kk] = 0.f;
    for (int nn = 0; nn < N_; nn++) {
        float a = g_A[nn * N_ + m];
        #pragma unroll
        for (int kk = 0; kk < 16; kk++) acc[kk] += rows[kk][nn] * a;
    }
    #pragma unroll
    for (int kk = 0; kk < 16; kk++)
        g_xglob[((size_t)b * K_ + kg * 16 + kk) * N_ + m] = acc[kk];
}

// ---------------- K5: mixed = LN( x + 0.5*rule + 0.5*kron , n1) ----------------
__global__ void k_mixed(const float* __restrict__ x,
                        const float* __restrict__ n1g, const float* __restrict__ n1b) {
    int row = blockIdx.x;
    int b = row >> 5, l = row & 31;
    int t = threadIdx.x;
    float v[4];
    float s1 = 0.f, s2 = 0.f;
    #pragma unroll
    for (int e = 0; e < 4; e++) {
        int d = t * 4 + e;
        float rule = x[((size_t)b * L_ + (d >> 5)) * D_ + l * 32 + (d & 31)];
        float kron = g_xglob[(size_t)row * D_ + d];
        float xv   = x[(size_t)row * D_ + d];
        float val = xv + 0.5f * rule + 0.5f * kron;
        v[e] = val; s1 += val; s2 += val * val;
    }
    blockReduce2_256(s1, s2);
    float m = s1 * (1.f / D_);
    float var = s2 * (1.f / D_) - m * m;
    float rs = rsqrtf(var + 1e-5f);
    #pragma unroll
    for (int e = 0; e < 4; e++) {
        int d = t * 4 + e;
        g_mixed[(size_t)row * D_ + d] = (v[e] - m) * rs * n1g[d] + n1b[d];
    }
}

// ---------------- tensor-core GEMM: C[64 x 128tile] = A[64 x K] * W[K x width] ----
// mode 0: A = g_mixed(l), K=1024, width=DFF, out = z ? g_U : g_G, W = z ? W1 : W0
// mode 1: A = g_H(l),     K=2048, width=D_,  out = g_ffn,          W = W0
// Split-bf16 (hi/lo) with 3 mma products for fp32-grade accuracy.
__global__ __launch_bounds__(256, 2) void k_gemm(const float* __restrict__ W0,
                                                 const float* __restrict__ W1,
                                                 int mode) {
    __shared__ unsigned Ah[16][72], Alo[16][72];     // [kpair][m]
    __shared__ unsigned Bh[16][136], Blo[16][136];   // [kpair][n]

    int l   = blockIdx.x;
    int nt0 = blockIdx.y * 128;
    int t   = threadIdx.x;

    const float* Ap; long lda; int Kdim, width;
    const float* Bp; float* Op;
    if (mode == 0) {
        Ap = g_mixed + (size_t)l * D_;  lda = (long)L_ * D_;  Kdim = D_;  width = DFF;
        const float* Wsel = blockIdx.z ? W1 : W0;
        Bp = Wsel + (size_t)l * D_ * DFF + nt0;
        Op = (blockIdx.z ? g_U : g_G) + (size_t)l * DFF + nt0;
    } else {
        Ap = g_H + (size_t)l * DFF;     lda = (long)L_ * DFF; Kdim = DFF; width = D_;
        Bp = W0 + (size_t)l * DFF * D_ + nt0;
        Op = g_ffn + (size_t)l * D_ + nt0;
    }

    int lane = t & 31, wid = t >> 5;
    int g = lane >> 2, tg = lane & 3;
    int wm = (wid & 1) * 32;          // warp m-offset (2 warps over M=64)
    int wn = (wid >> 1) * 32;         // warp n-offset (4 warps over N=128)

    float acc[2][4][4];
    #pragma unroll
    for (int mt = 0; mt < 2; mt++)
        #pragma unroll
        for (int nt = 0; nt < 4; nt++)
            #pragma unroll
            for (int e = 0; e < 4; e++) acc[mt][nt][e] = 0.f;

    for (int k0 = 0; k0 < Kdim; k0 += 32) {
        // ---- load + convert A tile: 64 x 32 fp32 -> hi/lo pairs [kp][m]
        #pragma unroll
        for (int q = t; q < 512; q += 256) {
            int m = q >> 3, f4 = q & 7;
            float4 v = *(const float4*)(Ap + (size_t)m * lda + k0 + f4 * 4);
            unsigned h0, l0, h1, l1;
            cvt_split(v.x, v.y, h0, l0);
            cvt_split(v.z, v.w, h1, l1);
            Ah[f4 * 2][m] = h0;  Alo[f4 * 2][m] = l0;
            Ah[f4 * 2 + 1][m] = h1; Alo[f4 * 2 + 1][m] = l1;
        }
        // ---- load + convert W tile: 32 x 128 fp32, pair consecutive k rows
        #pragma unroll
        for (int q = t; q < 512; q += 256) {
            int kp = q >> 5, n4 = (q & 31) * 4;
            const float* bp0 = Bp + (size_t)(k0 + 2 * kp) * width + n4;
            float4 u0 = *(const float4*)bp0;
            float4 u1 = *(const float4*)(bp0 + width);
            unsigned h, lo;
            cvt_split(u0.x, u1.x, h, lo); Bh[kp][n4 + 0] = h; Blo[kp][n4 + 0] = lo;
            cvt_split(u0.y, u1.y, h, lo); Bh[kp][n4 + 1] = h; Blo[kp][n4 + 1] = lo;
            cvt_split(u0.z, u1.z, h, lo); Bh[kp][n4 + 2] = h; Blo[kp][n4 + 2] = lo;
            cvt_split(u0.w, u1.w, h, lo); Bh[kp][n4 + 3] = h; Blo[kp][n4 + 3] = lo;
        }
        __syncthreads();

        #pragma unroll
        for (int s = 0; s < 2; s++) {
            int kp0 = s * 8 + tg, kp1 = kp0 + 4;
            unsigned afh[2][4], afl[2][4];
            #pragma unroll
            for (int mt = 0; mt < 2; mt++) {
                int r0 = wm + mt * 16 + g, r1 = r0 + 8;
                afh[mt][0] = Ah[kp0][r0];  afh[mt][1] = Ah[kp0][r1];
                afh[mt][2] = Ah[kp1][r0];  afh[mt][3] = Ah[kp1][r1];
                afl[mt][0] = Alo[kp0][r0]; afl[mt][1] = Alo[kp0][r1];
                afl[mt][2] = Alo[kp1][r0]; afl[mt][3] = Alo[kp1][r1];
            }
            #pragma unroll
            for (int nt = 0; nt < 4; nt++) {
                int cn = wn + nt * 8 + g;
                unsigned bh0 = Bh[kp0][cn], bh1 = Bh[kp1][cn];
                unsigned bl0 = Blo[kp0][cn], bl1 = Blo[kp1][cn];
                #pragma unroll
                for (int mt = 0; mt < 2; mt++) {
                    mma16816(acc[mt][nt], afh[mt], bh0, bh1);
                    mma16816(acc[mt][nt], afh[mt], bl0, bl1);
                    mma16816(acc[mt][nt], afl[mt], bh0, bh1);
                }
            }
        }
        __syncthreads();
    }

    // ---- epilogue: C[row=b][col] -> Op[b * (L_*width) + col]
    long ostride = (long)L_ * width;
    #pragma unroll
    for (int mt = 0; mt < 2; mt++) {
        int r0 = wm + mt * 16 + g;
        #pragma unroll
        for (int nt = 0; nt < 4; nt++) {
            int c = wn + nt * 8 + tg * 2;
            float* p0 = Op + (size_t)r0 * ostride + c;
            float* p1 = Op + (size_t)(r0 + 8) * ostride + c;
            *(float2*)p0 = make_float2(acc[mt][nt][0], acc[mt][nt][1]);
            *(float2*)p1 = make_float2(acc[mt][nt][2], acc[mt][nt][3]);
        }
    }
}

// ---------------- K6b: H = silu(G) * U ----------------
__global__ void k_act() {
    int idx = blockIdx.x * 256 + threadIdx.x;
    float4 g = ((const float4*)g_G)[idx];
    float4 u = ((const float4*)g_U)[idx];
    float4 h;
    h.x = g.x / (1.f + expf(-g.x)) * u.x;
    h.y = g.y / (1.f + expf(-g.y)) * u.y;
    h.z = g.z / (1.f + expf(-g.z)) * u.z;
    h.w = g.w / (1.f + expf(-g.w)) * u.w;
    ((float4*)g_H)[idx] = h;
}

// ---------------- K8: out = LN(mixed+ffn, n2); y_out = y + ffn ----------------
__global__ void k_final(const float* __restrict__ y,
                        const float* __restrict__ n2g, const float* __restrict__ n2b,
                        float* __restrict__ out) {
    int row = blockIdx.x;
    int t = threadIdx.x;
    float v[4], fv[4];
    float s1 = 0.f, s2 = 0.f;
    #pragma unroll
    for (int e = 0; e < 4; e++) {
        int d = t * 4 + e;
        size_t idx = (size_t)row * D_ + d;
        float f = g_ffn[idx];
        float val = g_mixed[idx] + f;
        v[e] = val; fv[e] = f; s1 += val; s2 += val * val;
    }
    blockReduce2_256(s1, s2);
    float m = s1 * (1.f / D_);
    float var = s2 * (1.f / D_) - m * m;
    float rs = rsqrtf(var + 1e-5f);
    #pragma unroll
    for (int e = 0; e < 4; e++) {
        int d = t * 4 + e;
        size_t idx = (size_t)row * D_ + d;
        out[idx] = (v[e] - m) * rs * n2g[d] + n2b[d];
        out[(size_t)B_ * L_ * D_ + idx] = y[idx] + fv[e];
    }
}

// ---------------- launch ----------------
extern "C" void kernel_launch(void* const* d_in, const int* in_sizes, int n_in,
                              void* d_out, int out_size) {
    const float* x       = (const float*)d_in[0];
    const float* y       = (const float*)d_in[1];
    const float* A_log   = (const float*)d_in[2];
    const float* W_1     = (const float*)d_in[3];
    const float* W_V     = (const float*)d_in[4];
    const float* kn1_g   = (const float*)d_in[5];
    const float* kn1_b   = (const float*)d_in[6];
    const float* kn2_g   = (const float*)d_in[7];
    const float* kn2_b   = (const float*)d_in[8];
    const float* W_gate  = (const float*)d_in[9];
    const float* W_up    = (const float*)d_in[10];
    const float* W_down  = (const float*)d_in[11];
    const float* ny_g    = (const float*)d_in[12];
    const float* ny_b    = (const float*)d_in[13];
    const float* n1_g    = (const float*)d_in[14];
    const float* n1_b    = (const float*)d_in[15];
    const float* n2_g    = (const float*)d_in[16];
    const float* n2_b    = (const float*)d_in[17];
    float* out = (float*)d_out;

    k_prepA<<<N_, 256>>>(A_log);
    k_prepW<<<N_, 128>>>(W_1, W_V);
    k_xr<<<B_ * L_, 256>>>(x, y, ny_g, ny_b, kn1_g, kn1_b);
    k_xlocal<<<dim3(N_, B_ / BG), 128>>>();
    k_trln<<<dim3(K_, B_), 256>>>(kn2_g, kn2_b);
    k_xglob<<<dim3(B_, 8), 256>>>();
    k_mixed<<<B_ * L_, 256>>>(x, n1_g, n1_b);
    k_gemm<<<dim3(L_, DFF / 128, 2), 256>>>(W_gate, W_up, 0);
    k_act<<<(B_ * L_ * DFF) / (256 * 4), 256>>>();
    k_gemm<<<dim3(L_, D_ / 128, 1), 256>>>(W_down, W_down, 1);
    k_final<<<B_ * L_, 256>>>(y, n2_g, n2_b, out);
}